// round 17
// baseline (speedup 1.0000x reference)
#include <cuda_runtime.h>
#include <cuda_bf16.h>
#include <cstdint>

// Problem constants
#define B_   32
#define C_   512
#define HW_  1024
#define R_   256

#define STRIDE 40                    // bf16 per smem row (32 data + 8 pad)
#define TILE_E (128 * STRIDE)        // elems per tile
#define TILE_B (TILE_E * 2)          // bytes per tile (10240)
#define STAGE_B (4 * TILE_B)         // AH, AL, BH, BL (40960)
#define SMEM_BYTES (2 * STAGE_B)     // 2 stages = 81920

// ---------------------------------------------------------------------------
// Scratch: all GEMM operands pre-split into hi/lo bf16 pairs
// ---------------------------------------------------------------------------
__device__ __nv_bfloat16 g_xT_h[16777216],   g_xT_l[16777216];    // [B][HW][C]
__device__ __nv_bfloat16 g_wkp_h[262144],    g_wkp_l[262144];     // [512][512] Wk|Wp
__device__ __nv_bfloat16 g_wv_h[262144],     g_wv_l[262144];      // [512][512]
__device__ __nv_bfloat16 g_projT_h[16777216], g_projT_l[16777216];// [B][HW][512]
__device__ __nv_bfloat16 g_val_h[16777216],  g_val_l[16777216];   // [B][512][HW]
__device__ float         g_energy[33554432];                      // [B][HW][HW] fp32
__device__ __nv_bfloat16 g_sim_h[33554432],  g_sim_l[33554432];   // [B][HW][HW]

// ---------------------------------------------------------------------------
// Helpers
// ---------------------------------------------------------------------------
__device__ __forceinline__ uint32_t s2u(const void* p) {
    uint32_t a;
    asm("{ .reg .u64 t; cvta.to.shared.u64 t, %1; cvt.u32.u64 %0, t; }"
        : "=r"(a) : "l"(p));
    return a;
}

__device__ __forceinline__ void mma16816(float* d, const uint32_t* a, const uint32_t* b) {
    asm volatile(
        "mma.sync.aligned.m16n8k16.row.col.f32.bf16.bf16.f32 "
        "{%0,%1,%2,%3}, {%4,%5,%6,%7}, {%8,%9}, {%0,%1,%2,%3};"
        : "+f"(d[0]), "+f"(d[1]), "+f"(d[2]), "+f"(d[3])
        : "r"(a[0]), "r"(a[1]), "r"(a[2]), "r"(a[3]), "r"(b[0]), "r"(b[1]));
}

__device__ __forceinline__ void ldmx4(uint32_t* r, uint32_t addr) {
    asm volatile("ldmatrix.sync.aligned.m8n8.x4.shared.b16 {%0,%1,%2,%3}, [%4];"
                 : "=r"(r[0]), "=r"(r[1]), "=r"(r[2]), "=r"(r[3]) : "r"(addr));
}

__device__ __forceinline__ void cpasync16(uint32_t dst, const __nv_bfloat16* src) {
    asm volatile("cp.async.ca.shared.global [%0], [%1], 16;"
                 :: "r"(dst), "l"(src));
}
#define CP_COMMIT() asm volatile("cp.async.commit_group;" ::: "memory")
#define CP_WAIT(n)  asm volatile("cp.async.wait_group %0;" :: "n"(n) : "memory")

// split fp32 pair -> hi/lo bf16x2 stores
__device__ __forceinline__ void store_hl2(__nv_bfloat16* ph, __nv_bfloat16* pl,
                                          float f0, float f1) {
    __nv_bfloat162 h = __floats2bfloat162_rn(f0, f1);
    __nv_bfloat162 l = __floats2bfloat162_rn(f0 - __bfloat162float(h.x),
                                             f1 - __bfloat162float(h.y));
    *(__nv_bfloat162*)ph = h;
    *(__nv_bfloat162*)pl = l;
}

__device__ __forceinline__ void split4(__nv_bfloat16* ph, __nv_bfloat16* pl, float4 v) {
    store_hl2(ph,     pl,     v.x, v.y);
    store_hl2(ph + 2, pl + 2, v.z, v.w);
}

// ---------------------------------------------------------------------------
// Stage loader: 4 tiles (AH, AL, BH, BL), 128x32 bf16 each, via cp.async.
// 256 threads: row = tid>>1, 16-col half (tid&1); 8 cp.async of 16B each.
// ---------------------------------------------------------------------------
__device__ __forceinline__ void load_stage(
    const __nv_bfloat16* aH, const __nv_bfloat16* aL, int aStride,
    const __nv_bfloat16* bH, const __nv_bfloat16* bL, int bStride,
    int kOff, uint32_t sb, int tid) {
    const int row = tid >> 1;
    const int col = (tid & 1) << 4;
    const uint32_t d  = sb + (uint32_t)(row * STRIDE + col) * 2;
    const size_t  ao = (size_t)row * aStride + kOff + col;
    const size_t  bo = (size_t)row * bStride + kOff + col;
    cpasync16(d,                aH + ao);
    cpasync16(d + 16,           aH + ao + 8);
    cpasync16(d + TILE_B,       aL + ao);
    cpasync16(d + TILE_B + 16,  aL + ao + 8);
    cpasync16(d + 2*TILE_B,     bH + bo);
    cpasync16(d + 2*TILE_B+16,  bH + bo + 8);
    cpasync16(d + 3*TILE_B,     bL + bo);
    cpasync16(d + 3*TILE_B+16,  bL + bo + 8);
}

// ---------------------------------------------------------------------------
// GEMM core: D[128][128] = sum_k A[128][K]*B[128][K], K = 32*nChunks.
// ALL 8 warps compute: 4x2 grid of 32x64 warp tiles (proven R11 mapping).
// cp.async 2-stage double buffer; 3-product bf16 split.
// ---------------------------------------------------------------------------
__device__ __forceinline__ void gemm_core(
    const __nv_bfloat16* aH, const __nv_bfloat16* aL, int aStride,
    const __nv_bfloat16* bH, const __nv_bfloat16* bL, int bStride,
    int nChunks, __nv_bfloat16* dsm, float acc[2][8][4]) {
    const int tid  = threadIdx.x;
    const int lane = tid & 31;
    const int wid  = tid >> 5;

    const int aro = (lane & 7) + ((lane >> 3) & 1) * 8;
    const int aco = ((lane >> 4) & 1) * 8;
    const int bro = ((lane >> 4) << 3) + (lane & 7);
    const int bco = ((lane >> 3) & 1) * 8;

    const int am = (wid & 3) * 32;
    const int bn = (wid >> 2) * 64;

    const uint32_t base = s2u(dsm);

    load_stage(aH, aL, aStride, bH, bL, bStride, 0, base, tid);
    CP_COMMIT();

    for (int ch = 0; ch < nChunks; ++ch) {
        if (ch + 1 < nChunks) {
            load_stage(aH, aL, aStride, bH, bL, bStride,
                       (ch + 1) * 32, base + (uint32_t)((ch + 1) & 1) * STAGE_B, tid);
            CP_COMMIT();
            CP_WAIT(1);
        } else {
            CP_WAIT(0);
        }
        __syncthreads();

        const uint32_t sb  = base + (uint32_t)(ch & 1) * STAGE_B;
        const uint32_t uAH = sb;
        const uint32_t uAL = sb + TILE_B;
        const uint32_t uBH = sb + 2 * TILE_B;
        const uint32_t uBL = sb + 3 * TILE_B;
        #pragma unroll
        for (int ks = 0; ks < 2; ++ks) {
            const int k0 = ks * 16;
            const uint32_t aoff = (uint32_t)((am + aro) * STRIDE + k0 + aco) * 2;
            uint32_t ah[2][4], al[2][4];
            ldmx4(ah[0], uAH + aoff);
            ldmx4(ah[1], uAH + aoff + 16 * STRIDE * 2);
            ldmx4(al[0], uAL + aoff);
            ldmx4(al[1], uAL + aoff + 16 * STRIDE * 2);

            const uint32_t boff = (uint32_t)((bn + bro) * STRIDE + k0 + bco) * 2;
            uint32_t bh[8][2], bl[8][2];
            #pragma unroll
            for (int g = 0; g < 4; ++g) {
                uint32_t r[4];
                ldmx4(r, uBH + boff + g * (16 * STRIDE * 2));
                bh[g*2][0] = r[0]; bh[g*2][1] = r[1];
                bh[g*2+1][0] = r[2]; bh[g*2+1][1] = r[3];
                ldmx4(r, uBL + boff + g * (16 * STRIDE * 2));
                bl[g*2][0] = r[0]; bl[g*2][1] = r[1];
                bl[g*2+1][0] = r[2]; bl[g*2+1][1] = r[3];
            }
            #pragma unroll
            for (int i = 0; i < 2; ++i)
                #pragma unroll
                for (int j = 0; j < 8; ++j) {
                    mma16816(acc[i][j], ah[i], bh[j]);
                    mma16816(acc[i][j], ah[i], bl[j]);
                    mma16816(acc[i][j], al[i], bh[j]);
                }
        }
        __syncthreads();
    }
}

#define DECL_ACC()                                                     \
    float acc[2][8][4];                                                \
    _Pragma("unroll") for (int i = 0; i < 2; ++i)                      \
        _Pragma("unroll") for (int j = 0; j < 8; ++j)                  \
            _Pragma("unroll") for (int q = 0; q < 4; ++q)              \
                acc[i][j][q] = 0.f;

// Epilogue mapping (all warps): 4x2 warp grid, 32x64 tiles (R11-proven)
#define EPI_M(i)  (((threadIdx.x >> 5) & 3) * 32 + (i) * 16 + ((threadIdx.x & 31) >> 2))
#define EPI_N(j)  (((threadIdx.x >> 5) >> 2) * 64 + (j) * 8 + ((threadIdx.x & 3) << 1))

// ---------------------------------------------------------------------------
// K-1: weight prep: Wk|Wp -> g_wkp hi/lo, Wv -> g_wv hi/lo
// ---------------------------------------------------------------------------
__global__ __launch_bounds__(256) void k_prep_w(
    const float* __restrict__ Wk, const float* __restrict__ Wp,
    const float* __restrict__ Wv) {
    const int idx = (blockIdx.x * 256 + threadIdx.x) * 4;
    const int row = idx >> 9, col = idx & 511;
    const float* src = (row < 256) ? (Wk + (size_t)row * 512 + col)
                                   : (Wp + (size_t)(row - 256) * 512 + col);
    split4(g_wkp_h + idx, g_wkp_l + idx, *(const float4*)src);
    split4(g_wv_h + idx, g_wv_l + idx, *(const float4*)(Wv + idx));
}

// ---------------------------------------------------------------------------
// K0: transpose+split x[b][c][m] -> xT hi/lo [b][m][c]
// ---------------------------------------------------------------------------
__global__ __launch_bounds__(256) void k_transpose(const float* __restrict__ x) {
    __shared__ float t[32][33];
    const int b = blockIdx.z;
    const int mB = blockIdx.x * 32, cB = blockIdx.y * 32;
    const int tx = threadIdx.x & 31, ty = threadIdx.x >> 5;
    const float* xb = x + ((size_t)b * C_ + cB) * HW_ + mB;
    #pragma unroll
    for (int j = 0; j < 32; j += 8)
        t[ty + j][tx] = xb[(size_t)(ty + j) * HW_ + tx];
    __syncthreads();
    const size_t ob = ((size_t)b * HW_ + mB) * C_ + cB;
    #pragma unroll
    for (int j = 0; j < 32; j += 8) {
        float f = t[tx][ty + j];
        __nv_bfloat16 h = __float2bfloat16(f);
        size_t o = ob + (size_t)(ty + j) * C_ + tx;
        g_xT_h[o] = h;
        g_xT_l[o] = __float2bfloat16(f - __bfloat162float(h));
    }
}

// ---------------------------------------------------------------------------
// K1a: projT[b][m][o] = sum_c xT[m,c]*Wkp[o,c] + bias[o]  (M=m, N=o, K=512)
// ---------------------------------------------------------------------------
__global__ __launch_bounds__(256) void k_proj_kp(
    const float* __restrict__ bk, const float* __restrict__ bp) {
    extern __shared__ __align__(16) __nv_bfloat16 dsm[];
    const int b = blockIdx.z, oBase = blockIdx.x * 128, mBase = blockIdx.y * 128;
    DECL_ACC();
    const size_t aOff = ((size_t)b * HW_ + mBase) * C_;
    const size_t bOff = (size_t)oBase * 512;
    gemm_core(g_xT_h + aOff, g_xT_l + aOff, C_,
              g_wkp_h + bOff, g_wkp_l + bOff, 512, 16, dsm, acc);

    const float* bias = (oBase < R_) ? (bk + oBase) : (bp + oBase - R_);
    #pragma unroll
    for (int i = 0; i < 2; ++i)
        #pragma unroll
        for (int j = 0; j < 8; ++j) {
            const int m0 = mBase + EPI_M(i);
            const int lc = EPI_N(j);
            const float b0 = bias[lc], b1 = bias[lc + 1];
            const size_t o0 = ((size_t)b * HW_ + m0) * 512 + oBase + lc;
            const size_t o1 = ((size_t)b * HW_ + m0 + 8) * 512 + oBase + lc;
            store_hl2(g_projT_h + o0, g_projT_l + o0,
                      acc[i][j][0] + b0, acc[i][j][1] + b1);
            store_hl2(g_projT_h + o1, g_projT_l + o1,
                      acc[i][j][2] + b0, acc[i][j][3] + b1);
        }
}

// ---------------------------------------------------------------------------
// K1b: val[b][c][m] = sum_cin Wv[c,cin]*xT[m,cin] + bv[c] (M=c, N=m, K=512)
// ---------------------------------------------------------------------------
__global__ __launch_bounds__(256) void k_proj_v(const float* __restrict__ bv) {
    extern __shared__ __align__(16) __nv_bfloat16 dsm[];
    const int b = blockIdx.z, mBase = blockIdx.x * 128, cBase = blockIdx.y * 128;
    DECL_ACC();
    const size_t aOff = (size_t)cBase * 512;
    const size_t bOff = ((size_t)b * HW_ + mBase) * C_;
    gemm_core(g_wv_h + aOff, g_wv_l + aOff, 512,
              g_xT_h + bOff, g_xT_l + bOff, C_, 16, dsm, acc);

    #pragma unroll
    for (int i = 0; i < 2; ++i)
        #pragma unroll
        for (int j = 0; j < 8; ++j) {
            const int c0 = cBase + EPI_M(i);
            const int lm = EPI_N(j);
            const float b0 = bv[c0], b1 = bv[c0 + 8];
            const size_t o0 = ((size_t)b * C_ + c0) * HW_ + mBase + lm;
            const size_t o1 = ((size_t)b * C_ + c0 + 8) * HW_ + mBase + lm;
            store_hl2(g_val_h + o0, g_val_l + o0,
                      acc[i][j][0] + b0, acc[i][j][1] + b0);
            store_hl2(g_val_h + o1, g_val_l + o1,
                      acc[i][j][2] + b1, acc[i][j][3] + b1);
        }
}

// ---------------------------------------------------------------------------
// K2: energy[b][n][m] = sum_r projT[n][r]*projT[m][256+r] (M=n, N=m, K=256)
// ---------------------------------------------------------------------------
__global__ __launch_bounds__(256) void k_energy_t() {
    extern __shared__ __align__(16) __nv_bfloat16 dsm[];
    const int b = blockIdx.z, mBase = blockIdx.x * 128, nBase = blockIdx.y * 128;
    DECL_ACC();
    const size_t aOff = ((size_t)b * HW_ + nBase) * 512;        // key
    const size_t bOff = ((size_t)b * HW_ + mBase) * 512 + R_;   // prod
    gemm_core(g_projT_h + aOff, g_projT_l + aOff, 512,
              g_projT_h + bOff, g_projT_l + bOff, 512, 8, dsm, acc);

    #pragma unroll
    for (int i = 0; i < 2; ++i)
        #pragma unroll
        for (int j = 0; j < 8; ++j) {
            const int n0 = nBase + EPI_M(i);
            const int lm = EPI_N(j);
            float* d0 = g_energy + ((size_t)b * HW_ + n0) * HW_ + mBase + lm;
            float* d1 = g_energy + ((size_t)b * HW_ + n0 + 8) * HW_ + mBase + lm;
            *(float2*)d0 = make_float2(acc[i][j][0], acc[i][j][1]);
            *(float2*)d1 = make_float2(acc[i][j][2], acc[i][j][3]);
        }
}

// ---------------------------------------------------------------------------
// K3: row softmax over energy (fp32) -> sim hi/lo
// ---------------------------------------------------------------------------
__global__ __launch_bounds__(256) void k_softmax() {
    const size_t row = blockIdx.x;
    const float* p = g_energy + row * HW_;
    const int tid = threadIdx.x, lane = tid & 31, wid = tid >> 5;
    __shared__ float redmax[8], redsum[8];

    float v[4];
    #pragma unroll
    for (int i = 0; i < 4; ++i) v[i] = p[tid + i * 256];

    float m = fmaxf(fmaxf(v[0], v[1]), fmaxf(v[2], v[3]));
    #pragma unroll
    for (int o = 16; o > 0; o >>= 1)
        m = fmaxf(m, __shfl_xor_sync(0xFFFFFFFFu, m, o));
    if (lane == 0) redmax[wid] = m;
    __syncthreads();
    m = redmax[0];
    #pragma unroll
    for (int i = 1; i < 8; ++i) m = fmaxf(m, redmax[i]);

    float s = 0.f;
    #pragma unroll
    for (int i = 0; i < 4; ++i) { v[i] = expf(v[i] - m); s += v[i]; }
    #pragma unroll
    for (int o = 16; o > 0; o >>= 1)
        s += __shfl_xor_sync(0xFFFFFFFFu, s, o);
    if (lane == 0) redsum[wid] = s;
    __syncthreads();
    s = 0.f;
    #pragma unroll
    for (int i = 0; i < 8; ++i) s += redsum[i];
    const float inv = 1.f / s;

    #pragma unroll
    for (int i = 0; i < 4; ++i) {
        float f = v[i] * inv;
        __nv_bfloat16 h = __float2bfloat16(f);
        size_t o = row * HW_ + tid + i * 256;
        g_sim_h[o] = h;
        g_sim_l[o] = __float2bfloat16(f - __bfloat162float(h));
    }
}

// ---------------------------------------------------------------------------
// K4: out = x + param * (val . simT)   (M=c, N=n, K=1024)
// ---------------------------------------------------------------------------
__global__ __launch_bounds__(256) void k_attn_out(
    const float* __restrict__ x, const float* __restrict__ param,
    float* __restrict__ out) {
    extern __shared__ __align__(16) __nv_bfloat16 dsm[];
    const int b = blockIdx.z, nBase = blockIdx.x * 128, cBase = blockIdx.y * 128;
    DECL_ACC();
    const size_t aOff = ((size_t)b * C_ + cBase) * HW_;
    const size_t bOff = ((size_t)b * HW_ + nBase) * HW_;
    gemm_core(g_val_h + aOff, g_val_l + aOff, HW_,
              g_sim_h + bOff, g_sim_l + bOff, HW_, 32, dsm, acc);

    const float ps = param[0];
    #pragma unroll
    for (int i = 0; i < 2; ++i)
        #pragma unroll
        for (int j = 0; j < 8; ++j) {
            const int c0 = cBase + EPI_M(i);
            const int ln = EPI_N(j);
            const size_t o0 = ((size_t)b * C_ + c0) * HW_ + nBase + ln;
            const size_t o1 = ((size_t)b * C_ + c0 + 8) * HW_ + nBase + ln;
            float2 x0 = *(const float2*)(x + o0);
            float2 x1 = *(const float2*)(x + o1);
            *(float2*)(out + o0) = make_float2(x0.x + ps * acc[i][j][0],
                                               x0.y + ps * acc[i][j][1]);
            *(float2*)(out + o1) = make_float2(x1.x + ps * acc[i][j][2],
                                               x1.y + ps * acc[i][j][3]);
        }
}

// ---------------------------------------------------------------------------
// Launch
// ---------------------------------------------------------------------------
extern "C" void kernel_launch(void* const* d_in, const int* in_sizes, int n_in,
                              void* d_out, int out_size) {
    const float* x     = (const float*)d_in[0];
    const float* Wk    = (const float*)d_in[1];
    const float* bk    = (const float*)d_in[2];
    const float* Wp    = (const float*)d_in[3];
    const float* bp    = (const float*)d_in[4];
    const float* Wv    = (const float*)d_in[5];
    const float* bv    = (const float*)d_in[6];
    const float* param = (const float*)d_in[7];
    float* out = (float*)d_out;

    cudaFuncSetAttribute(k_proj_kp,  cudaFuncAttributeMaxDynamicSharedMemorySize, SMEM_BYTES);
    cudaFuncSetAttribute(k_proj_v,   cudaFuncAttributeMaxDynamicSharedMemorySize, SMEM_BYTES);
    cudaFuncSetAttribute(k_energy_t, cudaFuncAttributeMaxDynamicSharedMemorySize, SMEM_BYTES);
    cudaFuncSetAttribute(k_attn_out, cudaFuncAttributeMaxDynamicSharedMemorySize, SMEM_BYTES);

    // K-1: weight split
    k_prep_w<<<256, 256>>>(Wk, Wp, Wv);

    // K0: x -> xT hi/lo
    k_transpose<<<dim3(HW_ / 32, C_ / 32, B_), 256>>>(x);

    // K1a: key+prod projections -> projT hi/lo
    k_proj_kp<<<dim3(4, 8, B_), 256, SMEM_BYTES>>>(bk, bp);

    // K1b: value projection -> val hi/lo
    k_proj_v<<<dim3(8, 4, B_), 256, SMEM_BYTES>>>(bv);

    // K2: energy (fp32)
    k_energy_t<<<dim3(8, 8, B_), 256, SMEM_BYTES>>>();

    // K3: softmax -> sim hi/lo
    k_softmax<<<B_ * HW_, 256>>>();

    // K4: attended + residual -> out
    k_attn_out<<<dim3(8, 4, B_), 256, SMEM_BYTES>>>(x, param, out);
}